// round 14
// baseline (speedup 1.0000x reference)
#include <cuda_runtime.h>
#include <cuda_fp16.h>
#include <cstdint>

#define B_   4
#define T_   4096
#define I_   1024
#define H_   16
#define D_   64
#define M_   (B_ * T_)        // 16384 rows (b,t)
#define NTOT 2048             // total N columns = H * 128
#define CH   32               // scan chunk length
#define NC   (T_ / CH)        // 128 chunks
#define NBH  (B_ * H_)        // 64 (b,h) pairs

#define KC   32               // K per pipeline stage
#define NST  (I_ / KC)        // 32 stages
#define STG  4                // ring depth

// ---------------- scratch (device globals: allocation-free) ----------------
__device__ __align__(16) __half g_a [(size_t)M_ * I_];   // 32 MB  A fp16
__device__ __align__(16) __half g_b [(size_t)I_ * NTOT]; // 4 MB   B [K][N] fp16
__device__ __align__(16) __half g_v [ (size_t)M_ * H_ * D_ ]; // 32 MB v fp16
__device__ __align__(16) float g_s [ (size_t)M_ * H_ ];      // 1 MB
__device__ float g_am[ NBH * NC ];
__device__ float g_au[ NBH * NC ];
__device__ float g_aw[ NBH * NC * D_ ];
__device__ float g_pm[ NBH * NC ];
__device__ float g_pu[ NBH * NC ];
__device__ float g_pw[ NBH * NC * D_ ];

// ---------------- helpers ----------------
__device__ __forceinline__ void ldsm_x4(uint32_t* r, const void* p) {
    uint32_t a = (uint32_t)__cvta_generic_to_shared(p);
    asm volatile("ldmatrix.sync.aligned.m8n8.x4.shared.b16 {%0,%1,%2,%3}, [%4];"
                 : "=r"(r[0]), "=r"(r[1]), "=r"(r[2]), "=r"(r[3]) : "r"(a));
}
__device__ __forceinline__ void ldsm_x2t(uint32_t* r, const void* p) {
    uint32_t a = (uint32_t)__cvta_generic_to_shared(p);
    asm volatile("ldmatrix.sync.aligned.m8n8.x2.trans.shared.b16 {%0,%1}, [%2];"
                 : "=r"(r[0]), "=r"(r[1]) : "r"(a));
}
__device__ __forceinline__ void mma16816(float* c, const uint32_t* a, const uint32_t* b) {
    asm volatile(
        "mma.sync.aligned.m16n8k16.row.col.f32.f16.f16.f32 "
        "{%0,%1,%2,%3}, {%4,%5,%6,%7}, {%8,%9}, {%0,%1,%2,%3};"
        : "+f"(c[0]), "+f"(c[1]), "+f"(c[2]), "+f"(c[3])
        : "r"(a[0]), "r"(a[1]), "r"(a[2]), "r"(a[3]), "r"(b[0]), "r"(b[1]));
}
__device__ __forceinline__ void cpa16(void* dst, const void* src) {
    uint32_t d = (uint32_t)__cvta_generic_to_shared(dst);
    asm volatile("cp.async.cg.shared.global [%0], [%1], 16;" :: "r"(d), "l"(src));
}
__device__ __forceinline__ uint32_t pack2h(__half a, __half b) {
    return (uint32_t)__half_as_ushort(a) | ((uint32_t)__half_as_ushort(b) << 16);
}

// ---------------------------------------------------------------------------
// Kernel 0: one-time fp32 -> fp16 convert of A and B.
// ---------------------------------------------------------------------------
#define NA4 ((size_t)M_ * I_ / 4)
#define NB4 ((size_t)I_ * NTOT / 4)
__global__ __launch_bounds__(256)
void k_split(const float* __restrict__ inp, const float* __restrict__ kvw)
{
    size_t i = (size_t)blockIdx.x * 256 + threadIdx.x;
    const float4* src;
    __half* dst;
    size_t o;
    if (i < NA4)            { src = (const float4*)inp; dst = g_a; o = i; }
    else if (i < NA4 + NB4) { src = (const float4*)kvw; dst = g_b; o = i - NA4; }
    else return;
    float4 x = src[o];
    ((uint2*)dst)[o] = make_uint2(
        pack2h(__float2half_rn(x.x), __float2half_rn(x.y)),
        pack2h(__float2half_rn(x.z), __float2half_rn(x.w)));
}

// ---------------------------------------------------------------------------
// Kernel 1: fp16 mma.sync GEMM (1-pass, fp32 acc) + silu + score + v-store
//           + fused per-chunk (CH=32) scan aggregates.
// Tile 128x256 (2 heads), 8 warps (2x4), KC=32, 4-stage cp.async ring.
// ---------------------------------------------------------------------------
struct GSmem {
    __half As[STG][128][40];   // 40960 B
    __half Bs[STG][KC][264];   // 67584 B
    float sred[2][128][2];
    float s_sh[2][128];
    float e_sh[2][128];
    float w_sh[2][4][64];      // [head][chunk32][d]
    float m_sh[2][4];
    float u_sh[2][4];
};

__global__ __launch_bounds__(256, 1)
void k_gemm_silu(const float* __restrict__ qw)
{
    extern __shared__ __align__(16) char smem_raw[];
    GSmem& S = *reinterpret_cast<GSmem*>(smem_raw);

    const int t    = threadIdx.x;
    const int warp = t >> 5, lane = t & 31;
    const int wm   = warp >> 2, wn = warp & 3;
    const int g    = lane >> 2, tg = lane & 3;
    const int m0   = blockIdx.x * 128;
    const int n0   = blockIdx.y * 256;

    float acc[4][8][4];
#pragma unroll
    for (int i = 0; i < 4; i++)
#pragma unroll
        for (int j = 0; j < 8; j++)
#pragma unroll
            for (int c = 0; c < 4; c++) acc[i][j][c] = 0.f;

    auto load_stage = [&](int st, int bf) {
        const size_t k0 = (size_t)st * KC;
#pragma unroll
        for (int q = 0; q < 2; q++) {
            int i = t + q * 256;
            int row = i >> 2, c16 = i & 3;
            size_t gi = (size_t)(m0 + row) * I_ + k0 + c16 * 8;
            cpa16(&S.As[bf][row][c16 * 8], g_a + gi);
        }
#pragma unroll
        for (int q = 0; q < 4; q++) {
            int i = t + q * 256;
            int row = i >> 5, c16 = i & 31;
            size_t gi = (size_t)(k0 + row) * NTOT + n0 + c16 * 8;
            cpa16(&S.Bs[bf][row][c16 * 8], g_b + gi);
        }
        asm volatile("cp.async.commit_group;");
    };

    const int arow = lane & 15;
    const int acol = (lane >> 4) * 8;

    load_stage(0, 0);
    load_stage(1, 1);
    load_stage(2, 2);

#pragma unroll 1
    for (int s = 0; s < NST; s++) {
        const int buf = s & 3;
        if (s <= NST - 3)      asm volatile("cp.async.wait_group 2;");
        else if (s == NST - 2) asm volatile("cp.async.wait_group 1;");
        else                   asm volatile("cp.async.wait_group 0;");
        __syncthreads();
        if (s + 3 < NST) load_stage(s + 3, (s + 3) & 3);

#pragma unroll
        for (int ks = 0; ks < 2; ks++) {
            uint32_t af[4][4];
#pragma unroll
            for (int it = 0; it < 4; it++)
                ldsm_x4(af[it], &S.As[buf][wm * 64 + it * 16 + arow][ks * 16 + acol]);
#pragma unroll
            for (int jt = 0; jt < 8; jt++) {
                uint32_t bf2[2];
                ldsm_x2t(bf2, &S.Bs[buf][ks * 16 + arow][wn * 64 + jt * 8]);
#pragma unroll
                for (int it = 0; it < 4; it++)
                    mma16816(acc[it][jt], af[it], bf2);
            }
        }
    }
    __syncthreads();

    // ---- epilogue: silu, v store (fp16), score partials ----
#pragma unroll
    for (int it = 0; it < 4; it++)
#pragma unroll
        for (int jt = 0; jt < 8; jt++)
#pragma unroll
            for (int c = 0; c < 4; c++) {
                float x = acc[it][jt][c];
                acc[it][jt][c] = __fdividef(x, 1.f + __expf(-x));
            }

    const int head_l = wn >> 1;
    const int head_g = blockIdx.y * 2 + head_l;
    float ps[4][2];
#pragma unroll
    for (int it = 0; it < 4; it++) { ps[it][0] = 0.f; ps[it][1] = 0.f; }

#pragma unroll
    for (int it = 0; it < 4; it++) {
        const int row0 = m0 + wm * 64 + it * 16 + g;
#pragma unroll
        for (int jt = 0; jt < 8; jt++) {
            const int d  = (wn & 1) * 32 + jt * 4 + tg;
            const float qv = qw[head_g * D_ + d];
            ps[it][0] += qv * acc[it][jt][0];
            ps[it][1] += qv * acc[it][jt][2];
            g_v[((size_t)row0       * H_ + head_g) * D_ + d] = __float2half_rn(acc[it][jt][1]);
            g_v[((size_t)(row0 + 8) * H_ + head_g) * D_ + d] = __float2half_rn(acc[it][jt][3]);
        }
    }
#pragma unroll
    for (int it = 0; it < 4; it++)
#pragma unroll
        for (int hh = 0; hh < 2; hh++) {
            float v = ps[it][hh];
            v += __shfl_xor_sync(0xffffffffu, v, 1);
            v += __shfl_xor_sync(0xffffffffu, v, 2);
            ps[it][hh] = v;
        }
    if (tg == 0) {
#pragma unroll
        for (int it = 0; it < 4; it++) {
            S.sred[head_l][wm * 64 + it * 16 + g    ][wn & 1] = ps[it][0];
            S.sred[head_l][wm * 64 + it * 16 + g + 8][wn & 1] = ps[it][1];
        }
    }
    __syncthreads();

    // s per (head, row)
    {
        const int hl  = t >> 7;
        const int row = t & 127;
        float s = S.sred[hl][row][0] + S.sred[hl][row][1];
        g_s[(size_t)(m0 + row) * H_ + blockIdx.y * 2 + hl] = s;
        S.s_sh[hl][row] = s;
    }
    __syncthreads();

    // per-32-row chunk max + expsum: warps 0,1 (one head each), 4 chunks
    if (warp < 2) {
#pragma unroll
        for (int c4 = 0; c4 < 4; c4++) {
            float s0 = S.s_sh[warp][c4 * 32 + lane];
            float mx = s0;
#pragma unroll
            for (int o = 16; o >= 1; o >>= 1)
                mx = fmaxf(mx, __shfl_xor_sync(0xffffffffu, mx, o));
            float e0 = __expf(s0 - mx);
            S.e_sh[warp][c4 * 32 + lane] = e0;
            float us = e0;
#pragma unroll
            for (int o = 16; o >= 1; o >>= 1)
                us += __shfl_xor_sync(0xffffffffu, us, o);
            if (lane == 0) { S.m_sh[warp][c4] = mx; S.u_sh[warp][c4] = us; }
        }
    }
    __syncthreads();

    // chunk w: warp rows wm*64..+63 span chunks 2*wm (its 0-1), 2*wm+1 (its 2-3).
    // Sequential passes with a scoped pw[8] to keep register pressure == R11.
#pragma unroll 1
    for (int cpass = 0; cpass < 2; cpass++) {
        float pw[8];
#pragma unroll
        for (int jt = 0; jt < 8; jt++) pw[jt] = 0.f;
#pragma unroll
        for (int iti = 0; iti < 2; iti++) {
            const int it = cpass * 2 + iti;
            const int r0 = wm * 64 + it * 16 + g;
            float e0 = S.e_sh[head_l][r0];
            float e1 = S.e_sh[head_l][r0 + 8];
#pragma unroll
            for (int jt = 0; jt < 8; jt++)
                pw[jt] = fmaf(e0, acc[it][jt][1], fmaf(e1, acc[it][jt][3], pw[jt]));
        }
#pragma unroll
        for (int jt = 0; jt < 8; jt++) {
            float v = pw[jt];
            v += __shfl_xor_sync(0xffffffffu, v, 4);
            v += __shfl_xor_sync(0xffffffffu, v, 8);
            v += __shfl_xor_sync(0xffffffffu, v, 16);
            pw[jt] = v;
        }
        if (g == 0) {
#pragma unroll
            for (int jt = 0; jt < 8; jt++)
                S.w_sh[head_l][wm * 2 + cpass][(wn & 1) * 32 + jt * 4 + tg] = pw[jt];
        }
    }
    __syncthreads();

    // write chunk aggregates: 2 heads x 4 chunks x 64 d = 512 entries
    {
        const int b  = m0 >> 12;
        const int cb = (m0 & 4095) >> 5;     // first chunk32 index of tile
#pragma unroll
        for (int q = 0; q < 2; q++) {
            const int idx2 = t + q * 256;
            const int hl   = idx2 >> 8;
            const int chk  = (idx2 >> 6) & 3;
            const int d    = idx2 & 63;
            const int hg   = blockIdx.y * 2 + hl;
            const int idx  = (b * H_ + hg) * NC + cb + chk;
            g_aw[idx * D_ + d] = S.w_sh[hl][chk][d];
            if (d == 0) { g_am[idx] = S.m_sh[hl][chk]; g_au[idx] = S.u_sh[hl][chk]; }
        }
    }
}

// ---------------------------------------------------------------------------
// Kernel 3: exclusive prefix over chunk aggregates (NC=128).
// ---------------------------------------------------------------------------
__global__ __launch_bounds__(64)
void k_prefix()
{
    const int bh = blockIdx.x;
    const int d  = threadIdx.x;
    float m = -1e30f, u = 0.f, w = 0.f;
    for (int c = 0; c < NC; c++) {
        const int idx = bh * NC + c;
        if (d == 0) { g_pm[idx] = m; g_pu[idx] = u; }
        g_pw[idx * D_ + d] = w;
        float am = g_am[idx];
        float au = g_au[idx];
        float aw = g_aw[idx * D_ + d];
        float mn = fmaxf(m, am);
        float ea = __expf(m  - mn);
        float eb = __expf(am - mn);
        u = u * ea + au * eb;
        w = w * ea + aw * eb;
        m = mn;
    }
}

// ---------------------------------------------------------------------------
// Kernel 4: apply — 2 d-lanes/thread, 8 heads/block (256 thr), CH=32, fp16 v.
// ---------------------------------------------------------------------------
__global__ __launch_bounds__(256)
void k_apply(float* __restrict__ out)
{
    const int c    = blockIdx.x;
    const int bh0  = blockIdx.y * 8;
    const int t    = threadIdx.x;
    const int hh   = t >> 5;            // 0..7 (bh within block)
    const int lane = t & 31;            // d pair index: d = 2*lane
    const int bh   = bh0 + hh;
    const int b    = bh >> 4;
    const int h    = bh & 15;
    const int t0   = c * CH;

    __shared__ float ssh[8][CH];
    {
        const int hx = t >> 5;
        const int i  = t & 31;
        const int bhx = bh0 + hx;
        ssh[hx][i] = g_s[(size_t)((bhx >> 4) * T_ + t0 + i) * H_ + (bhx & 15)];
    }
    __syncthreads();

    const int idx = bh * NC + c;
    float m = g_pm[idx];
    float u = g_pu[idx];
    float2 wv = *(const float2*)&g_pw[idx * D_ + 2 * lane];
    float w0 = wv.x, w1 = wv.y;

    const __half2* vp = (const __half2*)(g_v + ((size_t)(b * T_ + t0) * H_ + h) * D_ + 2 * lane);
    float2*        op = (float2*)(out + ((size_t)(b * T_ + t0) * H_ + h) * D_ + 2 * lane);
    const int      st = (H_ * D_) / 2;  // half2 stride per timestep

#pragma unroll 4
    for (int i = 0; i < CH; i++) {
        float s  = ssh[hh][i];
        float mn = fmaxf(m, s);
        float ea = __expf(m - mn);
        float eb = __expf(s - mn);
        u = u * ea + eb;
        float2 v2 = __half22float2(vp[(size_t)i * st]);
        w0 = fmaf(w0, ea, v2.x * eb);
        w1 = fmaf(w1, ea, v2.y * eb);
        m = mn;
        float r = __fdividef(1.f, u);
        op[(size_t)i * st] = make_float2(w0 * r, w1 * r);
    }
}

// ---------------------------------------------------------------------------
extern "C" void kernel_launch(void* const* d_in, const int* in_sizes, int n_in,
                              void* d_out, int out_size)
{
    const float* inp = (const float*)d_in[0];   // (B,T,I)
    const float* kvw = (const float*)d_in[1];   // (I,H,D,2)
    const float* qw  = (const float*)d_in[2];   // (H,D)
    float* out = (float*)d_out;                 // (B,T,H,D)

    static int init = 0;
    if (!init) {
        cudaFuncSetAttribute(k_gemm_silu,
                             cudaFuncAttributeMaxDynamicSharedMemorySize,
                             (int)sizeof(GSmem));
        init = 1;
    }

    const int nsplit = (int)((NA4 + NB4 + 255) / 256);
    k_split<<<nsplit, 256>>>(inp, kvw);
    k_gemm_silu<<<dim3(M_ / 128, NTOT / 256), 256, sizeof(GSmem)>>>(qw);
    k_prefix<<<NBH, 64>>>();
    k_apply <<<dim3(NC, NBH / 8), 256>>>(out);
}

// round 15
// speedup vs baseline: 3.9573x; 3.9573x over previous
#include <cuda_runtime.h>
#include <cuda_fp16.h>
#include <cstdint>

#define B_   4
#define T_   4096
#define I_   1024
#define H_   16
#define D_   64
#define M_   (B_ * T_)        // 16384 rows (b,t)
#define NTOT 2048             // total N columns = H * 128
#define CH   32               // scan chunk length
#define NC   (T_ / CH)        // 128 chunks
#define NBH  (B_ * H_)        // 64 (b,h) pairs

#define KC   32               // K per pipeline stage
#define NST  (I_ / KC)        // 32 stages
#define STG  4                // ring depth

// ---------------- scratch (device globals: allocation-free) ----------------
__device__ __align__(16) __half g_a [(size_t)M_ * I_];   // 32 MB  A fp16
__device__ __align__(16) __half g_b [(size_t)I_ * NTOT]; // 4 MB   B [K][N] fp16
__device__ __align__(16) __half g_v [ (size_t)M_ * H_ * D_ ]; // 32 MB v fp16
__device__ __align__(16) float g_s [ (size_t)M_ * H_ ];      // 1 MB
__device__ float g_am[ NBH * NC ];
__device__ float g_au[ NBH * NC ];
__device__ float g_aw[ NBH * NC * D_ ];
__device__ float g_pm[ NBH * NC ];
__device__ float g_pu[ NBH * NC ];
__device__ float g_pw[ NBH * NC * D_ ];

// ---------------- helpers ----------------
__device__ __forceinline__ void ldsm_x4(uint32_t* r, const void* p) {
    uint32_t a = (uint32_t)__cvta_generic_to_shared(p);
    asm volatile("ldmatrix.sync.aligned.m8n8.x4.shared.b16 {%0,%1,%2,%3}, [%4];"
                 : "=r"(r[0]), "=r"(r[1]), "=r"(r[2]), "=r"(r[3]) : "r"(a));
}
__device__ __forceinline__ void ldsm_x2t(uint32_t* r, const void* p) {
    uint32_t a = (uint32_t)__cvta_generic_to_shared(p);
    asm volatile("ldmatrix.sync.aligned.m8n8.x2.trans.shared.b16 {%0,%1}, [%2];"
                 : "=r"(r[0]), "=r"(r[1]) : "r"(a));
}
__device__ __forceinline__ void mma16816(float* c, const uint32_t* a, const uint32_t* b) {
    asm volatile(
        "mma.sync.aligned.m16n8k16.row.col.f32.f16.f16.f32 "
        "{%0,%1,%2,%3}, {%4,%5,%6,%7}, {%8,%9}, {%0,%1,%2,%3};"
        : "+f"(c[0]), "+f"(c[1]), "+f"(c[2]), "+f"(c[3])
        : "r"(a[0]), "r"(a[1]), "r"(a[2]), "r"(a[3]), "r"(b[0]), "r"(b[1]));
}
__device__ __forceinline__ void cpa16(void* dst, const void* src) {
    uint32_t d = (uint32_t)__cvta_generic_to_shared(dst);
    asm volatile("cp.async.cg.shared.global [%0], [%1], 16;" :: "r"(d), "l"(src));
}
__device__ __forceinline__ uint32_t pack2h(__half a, __half b) {
    return (uint32_t)__half_as_ushort(a) | ((uint32_t)__half_as_ushort(b) << 16);
}

// ---------------------------------------------------------------------------
// Kernel 0: one-time fp32 -> fp16 convert of A and B.
// ---------------------------------------------------------------------------
#define NA4 ((size_t)M_ * I_ / 4)
#define NB4 ((size_t)I_ * NTOT / 4)
__global__ __launch_bounds__(256)
void k_split(const float* __restrict__ inp, const float* __restrict__ kvw)
{
    size_t i = (size_t)blockIdx.x * 256 + threadIdx.x;
    const float4* src;
    __half* dst;
    size_t o;
    if (i < NA4)            { src = (const float4*)inp; dst = g_a; o = i; }
    else if (i < NA4 + NB4) { src = (const float4*)kvw; dst = g_b; o = i - NA4; }
    else return;
    float4 x = src[o];
    ((uint2*)dst)[o] = make_uint2(
        pack2h(__float2half_rn(x.x), __float2half_rn(x.y)),
        pack2h(__float2half_rn(x.z), __float2half_rn(x.w)));
}

// ---------------------------------------------------------------------------
// Kernel 1: fp16 mma.sync GEMM (1-pass, fp32 acc) + silu + score + v-store.
// Tile 128x256 (2 heads), 8 warps (2x4), KC=32, 4-stage cp.async ring.
// (No fused aggregates — k_agg computes them; keeps register pressure low.)
// ---------------------------------------------------------------------------
struct GSmem {
    __half As[STG][128][40];   // 40960 B
    __half Bs[STG][KC][264];   // 67584 B
    float sred[2][128][2];
};

__global__ __launch_bounds__(256, 1)
void k_gemm_silu(const float* __restrict__ qw)
{
    extern __shared__ __align__(16) char smem_raw[];
    GSmem& S = *reinterpret_cast<GSmem*>(smem_raw);

    const int t    = threadIdx.x;
    const int warp = t >> 5, lane = t & 31;
    const int wm   = warp >> 2, wn = warp & 3;
    const int g    = lane >> 2, tg = lane & 3;
    const int m0   = blockIdx.x * 128;
    const int n0   = blockIdx.y * 256;

    float acc[4][8][4];
#pragma unroll
    for (int i = 0; i < 4; i++)
#pragma unroll
        for (int j = 0; j < 8; j++)
#pragma unroll
            for (int c = 0; c < 4; c++) acc[i][j][c] = 0.f;

    auto load_stage = [&](int st, int bf) {
        const size_t k0 = (size_t)st * KC;
#pragma unroll
        for (int q = 0; q < 2; q++) {
            int i = t + q * 256;
            int row = i >> 2, c16 = i & 3;
            size_t gi = (size_t)(m0 + row) * I_ + k0 + c16 * 8;
            cpa16(&S.As[bf][row][c16 * 8], g_a + gi);
        }
#pragma unroll
        for (int q = 0; q < 4; q++) {
            int i = t + q * 256;
            int row = i >> 5, c16 = i & 31;
            size_t gi = (size_t)(k0 + row) * NTOT + n0 + c16 * 8;
            cpa16(&S.Bs[bf][row][c16 * 8], g_b + gi);
        }
        asm volatile("cp.async.commit_group;");
    };

    const int arow = lane & 15;
    const int acol = (lane >> 4) * 8;

    load_stage(0, 0);
    load_stage(1, 1);
    load_stage(2, 2);

#pragma unroll 1
    for (int s = 0; s < NST; s++) {
        const int buf = s & 3;
        if (s <= NST - 3)      asm volatile("cp.async.wait_group 2;");
        else if (s == NST - 2) asm volatile("cp.async.wait_group 1;");
        else                   asm volatile("cp.async.wait_group 0;");
        __syncthreads();
        if (s + 3 < NST) load_stage(s + 3, (s + 3) & 3);

#pragma unroll
        for (int ks = 0; ks < 2; ks++) {
            uint32_t af[4][4];
#pragma unroll
            for (int it = 0; it < 4; it++)
                ldsm_x4(af[it], &S.As[buf][wm * 64 + it * 16 + arow][ks * 16 + acol]);
#pragma unroll
            for (int jt = 0; jt < 8; jt++) {
                uint32_t bf2[2];
                ldsm_x2t(bf2, &S.Bs[buf][ks * 16 + arow][wn * 64 + jt * 8]);
#pragma unroll
                for (int it = 0; it < 4; it++)
                    mma16816(acc[it][jt], af[it], bf2);
            }
        }
    }
    __syncthreads();

    // ---- epilogue: silu, v store (fp16), score partials ----
#pragma unroll
    for (int it = 0; it < 4; it++)
#pragma unroll
        for (int jt = 0; jt < 8; jt++)
#pragma unroll
            for (int c = 0; c < 4; c++) {
                float x = acc[it][jt][c];
                acc[it][jt][c] = __fdividef(x, 1.f + __expf(-x));
            }

    const int head_l = wn >> 1;
    const int head_g = blockIdx.y * 2 + head_l;
    float ps[4][2];
#pragma unroll
    for (int it = 0; it < 4; it++) { ps[it][0] = 0.f; ps[it][1] = 0.f; }

#pragma unroll
    for (int it = 0; it < 4; it++) {
        const int row0 = m0 + wm * 64 + it * 16 + g;
#pragma unroll
        for (int jt = 0; jt < 8; jt++) {
            const int d  = (wn & 1) * 32 + jt * 4 + tg;
            const float qv = qw[head_g * D_ + d];
            ps[it][0] += qv * acc[it][jt][0];
            ps[it][1] += qv * acc[it][jt][2];
            g_v[((size_t)row0       * H_ + head_g) * D_ + d] = __float2half_rn(acc[it][jt][1]);
            g_v[((size_t)(row0 + 8) * H_ + head_g) * D_ + d] = __float2half_rn(acc[it][jt][3]);
        }
    }
#pragma unroll
    for (int it = 0; it < 4; it++)
#pragma unroll
        for (int hh = 0; hh < 2; hh++) {
            float v = ps[it][hh];
            v += __shfl_xor_sync(0xffffffffu, v, 1);
            v += __shfl_xor_sync(0xffffffffu, v, 2);
            ps[it][hh] = v;
        }
    if (tg == 0) {
#pragma unroll
        for (int it = 0; it < 4; it++) {
            S.sred[head_l][wm * 64 + it * 16 + g    ][wn & 1] = ps[it][0];
            S.sred[head_l][wm * 64 + it * 16 + g + 8][wn & 1] = ps[it][1];
        }
    }
    __syncthreads();

    // s per (head, row)
    {
        const int hl  = t >> 7;
        const int row = t & 127;
        float s = S.sred[hl][row][0] + S.sred[hl][row][1];
        g_s[(size_t)(m0 + row) * H_ + blockIdx.y * 2 + hl] = s;
    }
}

// ---------------------------------------------------------------------------
// Kernel 2: per-chunk (CH=32) aggregates from g_s + fp16 g_v.
// Grid (NC, NBH), 256 threads: 4 row-quarters x 64 d.
// ---------------------------------------------------------------------------
__global__ __launch_bounds__(256)
void k_agg()
{
    const int c  = blockIdx.x;
    const int bh = blockIdx.y;
    const int b  = bh >> 4;
    const int h  = bh & 15;
    const int t  = threadIdx.x;
    const int d  = t & 63;
    const int tq = t >> 6;           // 0..3, 8 rows each
    const int t0 = c * CH;

    __shared__ float ssh[CH];
    __shared__ float esh[CH];
    __shared__ float wred[4][D_];

    if (t < CH) ssh[t] = g_s[(size_t)(b * T_ + t0 + t) * H_ + h];
    __syncthreads();

    float m = -1e30f;
#pragma unroll
    for (int i = 0; i < CH; i++) m = fmaxf(m, ssh[i]);
    if (t < CH) esh[t] = __expf(ssh[t] - m);
    __syncthreads();

    float w = 0.f;
    const __half* vp = g_v + ((size_t)(b * T_ + t0 + tq * 8) * H_ + h) * D_ + d;
#pragma unroll
    for (int i = 0; i < 8; i++)
        w = fmaf(esh[tq * 8 + i], __half2float(vp[(size_t)i * (H_ * D_)]), w);
    wred[tq][d] = w;
    __syncthreads();

    const int idx = bh * NC + c;
    if (t < D_) {
        g_aw[idx * D_ + t] = wred[0][t] + wred[1][t] + wred[2][t] + wred[3][t];
        if (t == 0) {
            float u = 0.f;
#pragma unroll
            for (int i = 0; i < CH; i++) u += esh[i];
            g_am[idx] = m;
            g_au[idx] = u;
        }
    }
}

// ---------------------------------------------------------------------------
// Kernel 3: exclusive prefix over chunk aggregates (NC=128).
// ---------------------------------------------------------------------------
__global__ __launch_bounds__(64)
void k_prefix()
{
    const int bh = blockIdx.x;
    const int d  = threadIdx.x;
    float m = -1e30f, u = 0.f, w = 0.f;
    for (int c = 0; c < NC; c++) {
        const int idx = bh * NC + c;
        if (d == 0) { g_pm[idx] = m; g_pu[idx] = u; }
        g_pw[idx * D_ + d] = w;
        float am = g_am[idx];
        float au = g_au[idx];
        float aw = g_aw[idx * D_ + d];
        float mn = fmaxf(m, am);
        float ea = __expf(m  - mn);
        float eb = __expf(am - mn);
        u = u * ea + au * eb;
        w = w * ea + aw * eb;
        m = mn;
    }
}

// ---------------------------------------------------------------------------
// Kernel 4: apply — 2 d-lanes/thread, 8 heads/block (256 thr), CH=32, fp16 v.
// ---------------------------------------------------------------------------
__global__ __launch_bounds__(256)
void k_apply(float* __restrict__ out)
{
    const int c    = blockIdx.x;
    const int bh0  = blockIdx.y * 8;
    const int t    = threadIdx.x;
    const int hh   = t >> 5;            // 0..7 (bh within block)
    const int lane = t & 31;            // d pair index: d = 2*lane
    const int bh   = bh0 + hh;
    const int b    = bh >> 4;
    const int h    = bh & 15;
    const int t0   = c * CH;

    __shared__ float ssh[8][CH];
    {
        const int hx = t >> 5;
        const int i  = t & 31;
        const int bhx = bh0 + hx;
        ssh[hx][i] = g_s[(size_t)((bhx >> 4) * T_ + t0 + i) * H_ + (bhx & 15)];
    }
    __syncthreads();

    const int idx = bh * NC + c;
    float m = g_pm[idx];
    float u = g_pu[idx];
    float2 wv = *(const float2*)&g_pw[idx * D_ + 2 * lane];
    float w0 = wv.x, w1 = wv.y;

    const __half2* vp = (const __half2*)(g_v + ((size_t)(b * T_ + t0) * H_ + h) * D_ + 2 * lane);
    float2*        op = (float2*)(out + ((size_t)(b * T_ + t0) * H_ + h) * D_ + 2 * lane);
    const int      st = (H_ * D_) / 2;  // half2 stride per timestep

#pragma unroll 4
    for (int i = 0; i < CH; i++) {
        float s  = ssh[hh][i];
        float mn = fmaxf(m, s);
        float ea = __expf(m - mn);
        float eb = __expf(s - mn);
        u = u * ea + eb;
        float2 v2 = __half22float2(vp[(size_t)i * st]);
        w0 = fmaf(w0, ea, v2.x * eb);
        w1 = fmaf(w1, ea, v2.y * eb);
        m = mn;
        float r = __fdividef(1.f, u);
        op[(size_t)i * st] = make_float2(w0 * r, w1 * r);
    }
}

// ---------------------------------------------------------------------------
extern "C" void kernel_launch(void* const* d_in, const int* in_sizes, int n_in,
                              void* d_out, int out_size)
{
    const float* inp = (const float*)d_in[0];   // (B,T,I)
    const float* kvw = (const float*)d_in[1];   // (I,H,D,2)
    const float* qw  = (const float*)d_in[2];   // (H,D)
    float* out = (float*)d_out;                 // (B,T,H,D)

    static int init = 0;
    if (!init) {
        cudaFuncSetAttribute(k_gemm_silu,
                             cudaFuncAttributeMaxDynamicSharedMemorySize,
                             (int)sizeof(GSmem));
        init = 1;
    }

    const int nsplit = (int)((NA4 + NB4 + 255) / 256);
    k_split<<<nsplit, 256>>>(inp, kvw);
    k_gemm_silu<<<dim3(M_ / 128, NTOT / 256), 256, sizeof(GSmem)>>>(qw);
    k_agg   <<<dim3(NC, NBH), 256>>>();
    k_prefix<<<NBH, 64>>>();
    k_apply <<<dim3(NC, NBH / 8), 256>>>(out);
}

// round 16
// speedup vs baseline: 4.2514x; 1.0743x over previous
#include <cuda_runtime.h>
#include <cuda_fp16.h>
#include <cstdint>

#define B_   4
#define T_   4096
#define I_   1024
#define H_   16
#define D_   64
#define M_   (B_ * T_)        // 16384 rows (b,t)
#define NTOT 2048             // total N columns = H * 128
#define CH   32               // scan chunk length
#define NC   (T_ / CH)        // 128 chunks
#define NBH  (B_ * H_)        // 64 (b,h) pairs

#define KC   32               // K per pipeline stage
#define NST  (I_ / KC)        // 32 stages
#define STG  4                // ring depth

// ---------------- scratch (device globals: allocation-free) ----------------
__device__ __align__(16) __half g_a [(size_t)M_ * I_];   // 32 MB  A fp16
__device__ __align__(16) __half g_b [(size_t)I_ * NTOT]; // 4 MB   B [K][N] fp16
__device__ __align__(16) __half g_v [ (size_t)M_ * H_ * D_ ]; // 32 MB v fp16
__device__ __align__(16) float g_s [ (size_t)M_ * H_ ];      // 1 MB
__device__ float g_am[ NBH * NC ];
__device__ float g_au[ NBH * NC ];
__device__ float g_aw[ NBH * NC * D_ ];
__device__ float g_pm[ NBH * NC ];
__device__ float g_pu[ NBH * NC ];
__device__ float g_pw[ NBH * NC * D_ ];

// ---------------- helpers ----------------
__device__ __forceinline__ void ldsm_x4(uint32_t* r, const void* p) {
    uint32_t a = (uint32_t)__cvta_generic_to_shared(p);
    asm volatile("ldmatrix.sync.aligned.m8n8.x4.shared.b16 {%0,%1,%2,%3}, [%4];"
                 : "=r"(r[0]), "=r"(r[1]), "=r"(r[2]), "=r"(r[3]) : "r"(a));
}
__device__ __forceinline__ void ldsm_x2t(uint32_t* r, const void* p) {
    uint32_t a = (uint32_t)__cvta_generic_to_shared(p);
    asm volatile("ldmatrix.sync.aligned.m8n8.x2.trans.shared.b16 {%0,%1}, [%2];"
                 : "=r"(r[0]), "=r"(r[1]) : "r"(a));
}
__device__ __forceinline__ void mma16816(float* c, const uint32_t* a, const uint32_t* b) {
    asm volatile(
        "mma.sync.aligned.m16n8k16.row.col.f32.f16.f16.f32 "
        "{%0,%1,%2,%3}, {%4,%5,%6,%7}, {%8,%9}, {%0,%1,%2,%3};"
        : "+f"(c[0]), "+f"(c[1]), "+f"(c[2]), "+f"(c[3])
        : "r"(a[0]), "r"(a[1]), "r"(a[2]), "r"(a[3]), "r"(b[0]), "r"(b[1]));
}
__device__ __forceinline__ void cpa16(void* dst, const void* src) {
    uint32_t d = (uint32_t)__cvta_generic_to_shared(dst);
    asm volatile("cp.async.cg.shared.global [%0], [%1], 16;" :: "r"(d), "l"(src));
}
__device__ __forceinline__ uint32_t pack2h(__half a, __half b) {
    return (uint32_t)__half_as_ushort(a) | ((uint32_t)__half_as_ushort(b) << 16);
}

// ---------------------------------------------------------------------------
// Kernel 0: one-time fp32 -> fp16 convert of A and B.
// ---------------------------------------------------------------------------
#define NA4 ((size_t)M_ * I_ / 4)
#define NB4 ((size_t)I_ * NTOT / 4)
__global__ __launch_bounds__(256)
void k_split(const float* __restrict__ inp, const float* __restrict__ kvw)
{
    size_t i = (size_t)blockIdx.x * 256 + threadIdx.x;
    const float4* src;
    __half* dst;
    size_t o;
    if (i < NA4)            { src = (const float4*)inp; dst = g_a; o = i; }
    else if (i < NA4 + NB4) { src = (const float4*)kvw; dst = g_b; o = i - NA4; }
    else return;
    float4 x = src[o];
    ((uint2*)dst)[o] = make_uint2(
        pack2h(__float2half_rn(x.x), __float2half_rn(x.y)),
        pack2h(__float2half_rn(x.z), __float2half_rn(x.w)));
}

// ---------------------------------------------------------------------------
// Kernel 1: fp16 mma.sync GEMM (1-pass, fp32 acc) + silu + score + v-store.
// Tile 128x256 (2 heads), 8 warps (2x4), KC=32, 4-stage cp.async ring.
// ---------------------------------------------------------------------------
struct GSmem {
    __half As[STG][128][40];   // 40960 B
    __half Bs[STG][KC][264];   // 67584 B
    float sred[2][128][2];
};

__global__ __launch_bounds__(256, 1)
void k_gemm_silu(const float* __restrict__ qw)
{
    extern __shared__ __align__(16) char smem_raw[];
    GSmem& S = *reinterpret_cast<GSmem*>(smem_raw);

    const int t    = threadIdx.x;
    const int warp = t >> 5, lane = t & 31;
    const int wm   = warp >> 2, wn = warp & 3;
    const int g    = lane >> 2, tg = lane & 3;
    const int m0   = blockIdx.x * 128;
    const int n0   = blockIdx.y * 256;

    float acc[4][8][4];
#pragma unroll
    for (int i = 0; i < 4; i++)
#pragma unroll
        for (int j = 0; j < 8; j++)
#pragma unroll
            for (int c = 0; c < 4; c++) acc[i][j][c] = 0.f;

    auto load_stage = [&](int st, int bf) {
        const size_t k0 = (size_t)st * KC;
#pragma unroll
        for (int q = 0; q < 2; q++) {
            int i = t + q * 256;
            int row = i >> 2, c16 = i & 3;
            size_t gi = (size_t)(m0 + row) * I_ + k0 + c16 * 8;
            cpa16(&S.As[bf][row][c16 * 8], g_a + gi);
        }
#pragma unroll
        for (int q = 0; q < 4; q++) {
            int i = t + q * 256;
            int row = i >> 5, c16 = i & 31;
            size_t gi = (size_t)(k0 + row) * NTOT + n0 + c16 * 8;
            cpa16(&S.Bs[bf][row][c16 * 8], g_b + gi);
        }
        asm volatile("cp.async.commit_group;");
    };

    const int arow = lane & 15;
    const int acol = (lane >> 4) * 8;

    load_stage(0, 0);
    load_stage(1, 1);
    load_stage(2, 2);

#pragma unroll 1
    for (int s = 0; s < NST; s++) {
        const int buf = s & 3;
        if (s <= NST - 3)      asm volatile("cp.async.wait_group 2;");
        else if (s == NST - 2) asm volatile("cp.async.wait_group 1;");
        else                   asm volatile("cp.async.wait_group 0;");
        __syncthreads();
        if (s + 3 < NST) load_stage(s + 3, (s + 3) & 3);

#pragma unroll
        for (int ks = 0; ks < 2; ks++) {
            uint32_t af[4][4];
#pragma unroll
            for (int it = 0; it < 4; it++)
                ldsm_x4(af[it], &S.As[buf][wm * 64 + it * 16 + arow][ks * 16 + acol]);
#pragma unroll
            for (int jt = 0; jt < 8; jt++) {
                uint32_t bf2[2];
                ldsm_x2t(bf2, &S.Bs[buf][ks * 16 + arow][wn * 64 + jt * 8]);
#pragma unroll
                for (int it = 0; it < 4; it++)
                    mma16816(acc[it][jt], af[it], bf2);
            }
        }
    }
    __syncthreads();

    // ---- epilogue: silu, v store (fp16), score partials ----
#pragma unroll
    for (int it = 0; it < 4; it++)
#pragma unroll
        for (int jt = 0; jt < 8; jt++)
#pragma unroll
            for (int c = 0; c < 4; c++) {
                float x = acc[it][jt][c];
                acc[it][jt][c] = __fdividef(x, 1.f + __expf(-x));
            }

    const int head_l = wn >> 1;
    const int head_g = blockIdx.y * 2 + head_l;
    float ps[4][2];
#pragma unroll
    for (int it = 0; it < 4; it++) { ps[it][0] = 0.f; ps[it][1] = 0.f; }

#pragma unroll
    for (int it = 0; it < 4; it++) {
        const int row0 = m0 + wm * 64 + it * 16 + g;
#pragma unroll
        for (int jt = 0; jt < 8; jt++) {
            const int d  = (wn & 1) * 32 + jt * 4 + tg;
            const float qv = qw[head_g * D_ + d];
            ps[it][0] += qv * acc[it][jt][0];
            ps[it][1] += qv * acc[it][jt][2];
            g_v[((size_t)row0       * H_ + head_g) * D_ + d] = __float2half_rn(acc[it][jt][1]);
            g_v[((size_t)(row0 + 8) * H_ + head_g) * D_ + d] = __float2half_rn(acc[it][jt][3]);
        }
    }
#pragma unroll
    for (int it = 0; it < 4; it++)
#pragma unroll
        for (int hh = 0; hh < 2; hh++) {
            float v = ps[it][hh];
            v += __shfl_xor_sync(0xffffffffu, v, 1);
            v += __shfl_xor_sync(0xffffffffu, v, 2);
            ps[it][hh] = v;
        }
    if (tg == 0) {
#pragma unroll
        for (int it = 0; it < 4; it++) {
            S.sred[head_l][wm * 64 + it * 16 + g    ][wn & 1] = ps[it][0];
            S.sred[head_l][wm * 64 + it * 16 + g + 8][wn & 1] = ps[it][1];
        }
    }
    __syncthreads();

    {
        const int hl  = t >> 7;
        const int row = t & 127;
        float s = S.sred[hl][row][0] + S.sred[hl][row][1];
        g_s[(size_t)(m0 + row) * H_ + blockIdx.y * 2 + hl] = s;
    }
}

// ---------------------------------------------------------------------------
// Kernel 2: per-chunk (CH=32) aggregates from g_s + fp16 g_v.
// Grid (NC, NBH), 256 threads: 4 row-quarters x 64 d.
// ---------------------------------------------------------------------------
__global__ __launch_bounds__(256)
void k_agg()
{
    const int c  = blockIdx.x;
    const int bh = blockIdx.y;
    const int b  = bh >> 4;
    const int h  = bh & 15;
    const int t  = threadIdx.x;
    const int d  = t & 63;
    const int tq = t >> 6;           // 0..3, 8 rows each
    const int t0 = c * CH;

    __shared__ float ssh[CH];
    __shared__ float esh[CH];
    __shared__ float wred[4][D_];

    if (t < CH) ssh[t] = g_s[(size_t)(b * T_ + t0 + t) * H_ + h];
    __syncthreads();

    float m = -1e30f;
#pragma unroll
    for (int i = 0; i < CH; i++) m = fmaxf(m, ssh[i]);
    if (t < CH) esh[t] = __expf(ssh[t] - m);
    __syncthreads();

    float w = 0.f;
    const __half* vp = g_v + ((size_t)(b * T_ + t0 + tq * 8) * H_ + h) * D_ + d;
#pragma unroll
    for (int i = 0; i < 8; i++)
        w = fmaf(esh[tq * 8 + i], __half2float(vp[(size_t)i * (H_ * D_)]), w);
    wred[tq][d] = w;
    __syncthreads();

    const int idx = bh * NC + c;
    if (t < D_) {
        g_aw[idx * D_ + t] = wred[0][t] + wred[1][t] + wred[2][t] + wred[3][t];
        if (t == 0) {
            float u = 0.f;
#pragma unroll
            for (int i = 0; i < CH; i++) u += esh[i];
            g_am[idx] = m;
            g_au[idx] = u;
        }
    }
}

// ---------------------------------------------------------------------------
// Kernel 3: PARALLEL exclusive prefix — Hillis-Steele scan in smem.
// One block per bh, 256 threads, ping-pong buffers, 7 steps (NC=128).
// ---------------------------------------------------------------------------
struct PSmem {
    float w[2][NC][D_];   // 65536 B
    float m[2][NC];       // 1024 B
    float u[2][NC];       // 1024 B
    float ea[NC];         // 512 B
    float eb[NC];         // 512 B
};

__global__ __launch_bounds__(256)
void k_prefix()
{
    extern __shared__ __align__(16) char psm_raw[];
    PSmem& P = *reinterpret_cast<PSmem*>(psm_raw);

    const int bh = blockIdx.x;
    const int t  = threadIdx.x;

    // load aggregates
    if (t < NC) {
        P.m[0][t] = g_am[bh * NC + t];
        P.u[0][t] = g_au[bh * NC + t];
    }
    {
        const float4* src = (const float4*)&g_aw[(size_t)bh * NC * D_];
        float4* dst = (float4*)&P.w[0][0][0];
#pragma unroll
        for (int q = 0; q < (NC * D_ / 4) / 256; q++)   // 8
            dst[t + q * 256] = src[t + q * 256];
    }
    __syncthreads();

    int buf = 0;
#pragma unroll
    for (int k = 1; k < NC; k <<= 1) {
        if (t < NC) {
            float mb = P.m[buf][t], ub = P.u[buf][t];
            if (t >= k) {
                float ma = P.m[buf][t - k], ua = P.u[buf][t - k];
                float mn = fmaxf(ma, mb);
                float ea = __expf(ma - mn);
                float eb = __expf(mb - mn);
                P.m[buf ^ 1][t] = mn;
                P.u[buf ^ 1][t] = ua * ea + ub * eb;
                P.ea[t] = ea;
                P.eb[t] = eb;
            } else {
                P.m[buf ^ 1][t] = mb;
                P.u[buf ^ 1][t] = ub;
                P.ea[t] = 0.f;
                P.eb[t] = 1.f;
            }
        }
        __syncthreads();
#pragma unroll
        for (int q = 0; q < NC * D_ / 256; q++) {       // 32
            int idx2 = t + q * 256;
            int c = idx2 >> 6, d = idx2 & 63;
            float wb = P.w[buf][c][d];
            float wa = (c >= k) ? P.w[buf][c - k][d] : 0.f;
            P.w[buf ^ 1][c][d] = fmaf(wa, P.ea[c], wb * P.eb[c]);
        }
        __syncthreads();
        buf ^= 1;
    }

    // write EXCLUSIVE prefix (shift by one chunk)
    if (t < NC) {
        g_pm[bh * NC + t] = (t == 0) ? -1e30f : P.m[buf][t - 1];
        g_pu[bh * NC + t] = (t == 0) ? 0.f    : P.u[buf][t - 1];
    }
#pragma unroll
    for (int q = 0; q < NC * D_ / 256; q++) {
        int idx2 = t + q * 256;
        int c = idx2 >> 6, d = idx2 & 63;
        g_pw[((size_t)bh * NC + c) * D_ + d] = (c == 0) ? 0.f : P.w[buf][c - 1][d];
    }
}

// ---------------------------------------------------------------------------
// Kernel 4: apply — 2 d-lanes/thread, 8 heads/block (256 thr), CH=32, fp16 v.
// ---------------------------------------------------------------------------
__global__ __launch_bounds__(256)
void k_apply(float* __restrict__ out)
{
    const int c    = blockIdx.x;
    const int bh0  = blockIdx.y * 8;
    const int t    = threadIdx.x;
    const int hh   = t >> 5;
    const int lane = t & 31;
    const int bh   = bh0 + hh;
    const int b    = bh >> 4;
    const int h    = bh & 15;
    const int t0   = c * CH;

    __shared__ float ssh[8][CH];
    {
        const int hx = t >> 5;
        const int i  = t & 31;
        const int bhx = bh0 + hx;
        ssh[hx][i] = g_s[(size_t)((bhx >> 4) * T_ + t0 + i) * H_ + (bhx & 15)];
    }
    __syncthreads();

    const int idx = bh * NC + c;
    float m = g_pm[idx];
    float u = g_pu[idx];
    float2 wv = *(const float2*)&g_pw[idx * D_ + 2 * lane];
    float w0 = wv.x, w1 = wv.y;

    const __half2* vp = (const __half2*)(g_v + ((size_t)(b * T_ + t0) * H_ + h) * D_ + 2 * lane);
    float2*        op = (float2*)(out + ((size_t)(b * T_ + t0) * H_ + h) * D_ + 2 * lane);
    const int      st = (H_ * D_) / 2;

#pragma unroll 4
    for (int i = 0; i < CH; i++) {
        float s  = ssh[hh][i];
        float mn = fmaxf(m, s);
        float ea = __expf(m - mn);
        float eb = __expf(s - mn);
        u = u * ea + eb;
        float2 v2 = __half22float2(vp[(size_t)i * st]);
        w0 = fmaf(w0, ea, v2.x * eb);
        w1 = fmaf(w1, ea, v2.y * eb);
        m = mn;
        float r = __fdividef(1.f, u);
        op[(size_t)i * st] = make_float2(w0 * r, w1 * r);
    }
}

// ---------------------------------------------------------------------------
extern "C" void kernel_launch(void* const* d_in, const int* in_sizes, int n_in,
                              void* d_out, int out_size)
{
    const float* inp = (const float*)d_in[0];   // (B,T,I)
    const float* kvw = (const float*)d_in[1];   // (I,H,D,2)
    const float* qw  = (const float*)d_in[2];   // (H,D)
    float* out = (float*)d_out;                 // (B,T,H,D)

    static int init = 0;
    if (!init) {
        cudaFuncSetAttribute(k_gemm_silu,
                             cudaFuncAttributeMaxDynamicSharedMemorySize,
                             (int)sizeof(GSmem));
        cudaFuncSetAttribute(k_prefix,
                             cudaFuncAttributeMaxDynamicSharedMemorySize,
                             (int)sizeof(PSmem));
        init = 1;
    }

    const int nsplit = (int)((NA4 + NB4 + 255) / 256);
    k_split<<<nsplit, 256>>>(inp, kvw);
    k_gemm_silu<<<dim3(M_ / 128, NTOT / 256), 256, sizeof(GSmem)>>>(qw);
    k_agg   <<<dim3(NC, NBH), 256>>>();
    k_prefix<<<NBH, 256, sizeof(PSmem)>>>();
    k_apply <<<dim3(NC, NBH / 8), 256>>>(out);
}

// round 17
// speedup vs baseline: 4.3050x; 1.0126x over previous
#include <cuda_runtime.h>
#include <cuda_fp16.h>
#include <cstdint>

#define B_   4
#define T_   4096
#define I_   1024
#define H_   16
#define D_   64
#define M_   (B_ * T_)        // 16384 rows (b,t)
#define NTOT 2048             // total N columns = H * 128
#define CH   32               // scan chunk length
#define NC   (T_ / CH)        // 128 chunks
#define NBH  (B_ * H_)        // 64 (b,h) pairs

#define KC   32               // K per pipeline stage
#define NST  (I_ / KC)        // 32 stages
#define STG  4                // ring depth

// ---------------- scratch (device globals: allocation-free) ----------------
__device__ __align__(16) __half g_a [(size_t)M_ * I_];   // 32 MB  A fp16
__device__ __align__(16) __half g_b [(size_t)I_ * NTOT]; // 4 MB   B [K][N] fp16
__device__ __align__(16) __half g_v [ (size_t)M_ * H_ * D_ ]; // 32 MB v fp16
__device__ __align__(16) float g_s [ (size_t)M_ * H_ ];      // 1 MB scores
__device__ __align__(16) float g_e [ (size_t)M_ * H_ ];      // 1 MB exp(s - m_chunk)
__device__ float g_am[ NBH * NC ];
__device__ float g_au[ NBH * NC ];
__device__ float g_aw[ NBH * NC * D_ ];
__device__ float g_pm[ NBH * NC ];
__device__ float g_pu[ NBH * NC ];
__device__ float g_pw[ NBH * NC * D_ ];

// ---------------- helpers ----------------
__device__ __forceinline__ void ldsm_x4(uint32_t* r, const void* p) {
    uint32_t a = (uint32_t)__cvta_generic_to_shared(p);
    asm volatile("ldmatrix.sync.aligned.m8n8.x4.shared.b16 {%0,%1,%2,%3}, [%4];"
                 : "=r"(r[0]), "=r"(r[1]), "=r"(r[2]), "=r"(r[3]) : "r"(a));
}
__device__ __forceinline__ void ldsm_x2t(uint32_t* r, const void* p) {
    uint32_t a = (uint32_t)__cvta_generic_to_shared(p);
    asm volatile("ldmatrix.sync.aligned.m8n8.x2.trans.shared.b16 {%0,%1}, [%2];"
                 : "=r"(r[0]), "=r"(r[1]) : "r"(a));
}
__device__ __forceinline__ void mma16816(float* c, const uint32_t* a, const uint32_t* b) {
    asm volatile(
        "mma.sync.aligned.m16n8k16.row.col.f32.f16.f16.f32 "
        "{%0,%1,%2,%3}, {%4,%5,%6,%7}, {%8,%9}, {%0,%1,%2,%3};"
        : "+f"(c[0]), "+f"(c[1]), "+f"(c[2]), "+f"(c[3])
        : "r"(a[0]), "r"(a[1]), "r"(a[2]), "r"(a[3]), "r"(b[0]), "r"(b[1]));
}
__device__ __forceinline__ void cpa16(void* dst, const void* src) {
    uint32_t d = (uint32_t)__cvta_generic_to_shared(dst);
    asm volatile("cp.async.cg.shared.global [%0], [%1], 16;" :: "r"(d), "l"(src));
}
__device__ __forceinline__ uint32_t pack2h(__half a, __half b) {
    return (uint32_t)__half_as_ushort(a) | ((uint32_t)__half_as_ushort(b) << 16);
}

// ---------------------------------------------------------------------------
// Kernel 0: one-time fp32 -> fp16 convert of A and B.
// ---------------------------------------------------------------------------
#define NA4 ((size_t)M_ * I_ / 4)
#define NB4 ((size_t)I_ * NTOT / 4)
__global__ __launch_bounds__(256)
void k_split(const float* __restrict__ inp, const float* __restrict__ kvw)
{
    size_t i = (size_t)blockIdx.x * 256 + threadIdx.x;
    const float4* src;
    __half* dst;
    size_t o;
    if (i < NA4)            { src = (const float4*)inp; dst = g_a; o = i; }
    else if (i < NA4 + NB4) { src = (const float4*)kvw; dst = g_b; o = i - NA4; }
    else return;
    float4 x = src[o];
    ((uint2*)dst)[o] = make_uint2(
        pack2h(__float2half_rn(x.x), __float2half_rn(x.y)),
        pack2h(__float2half_rn(x.z), __float2half_rn(x.w)));
}

// ---------------------------------------------------------------------------
// Kernel 1: fp16 mma.sync GEMM (1-pass, fp32 acc) + silu + score + v-store.
// Tile 128x256 (2 heads), 8 warps (2x4), KC=32, 4-stage cp.async ring.
// ---------------------------------------------------------------------------
struct GSmem {
    __half As[STG][128][40];   // 40960 B
    __half Bs[STG][KC][264];   // 67584 B
    float sred[2][128][2];
};

__global__ __launch_bounds__(256, 1)
void k_gemm_silu(const float* __restrict__ qw)
{
    extern __shared__ __align__(16) char smem_raw[];
    GSmem& S = *reinterpret_cast<GSmem*>(smem_raw);

    const int t    = threadIdx.x;
    const int warp = t >> 5, lane = t & 31;
    const int wm   = warp >> 2, wn = warp & 3;
    const int g    = lane >> 2, tg = lane & 3;
    const int m0   = blockIdx.x * 128;
    const int n0   = blockIdx.y * 256;

    float acc[4][8][4];
#pragma unroll
    for (int i = 0; i < 4; i++)
#pragma unroll
        for (int j = 0; j < 8; j++)
#pragma unroll
            for (int c = 0; c < 4; c++) acc[i][j][c] = 0.f;

    auto load_stage = [&](int st, int bf) {
        const size_t k0 = (size_t)st * KC;
#pragma unroll
        for (int q = 0; q < 2; q++) {
            int i = t + q * 256;
            int row = i >> 2, c16 = i & 3;
            size_t gi = (size_t)(m0 + row) * I_ + k0 + c16 * 8;
            cpa16(&S.As[bf][row][c16 * 8], g_a + gi);
        }
#pragma unroll
        for (int q = 0; q < 4; q++) {
            int i = t + q * 256;
            int row = i >> 5, c16 = i & 31;
            size_t gi = (size_t)(k0 + row) * NTOT + n0 + c16 * 8;
            cpa16(&S.Bs[bf][row][c16 * 8], g_b + gi);
        }
        asm volatile("cp.async.commit_group;");
    };

    const int arow = lane & 15;
    const int acol = (lane >> 4) * 8;

    load_stage(0, 0);
    load_stage(1, 1);
    load_stage(2, 2);

#pragma unroll 1
    for (int s = 0; s < NST; s++) {
        const int buf = s & 3;
        if (s <= NST - 3)      asm volatile("cp.async.wait_group 2;");
        else if (s == NST - 2) asm volatile("cp.async.wait_group 1;");
        else                   asm volatile("cp.async.wait_group 0;");
        __syncthreads();
        if (s + 3 < NST) load_stage(s + 3, (s + 3) & 3);

#pragma unroll
        for (int ks = 0; ks < 2; ks++) {
            uint32_t af[4][4];
#pragma unroll
            for (int it = 0; it < 4; it++)
                ldsm_x4(af[it], &S.As[buf][wm * 64 + it * 16 + arow][ks * 16 + acol]);
#pragma unroll
            for (int jt = 0; jt < 8; jt++) {
                uint32_t bf2[2];
                ldsm_x2t(bf2, &S.Bs[buf][ks * 16 + arow][wn * 64 + jt * 8]);
#pragma unroll
                for (int it = 0; it < 4; it++)
                    mma16816(acc[it][jt], af[it], bf2);
            }
        }
    }
    __syncthreads();

    // ---- epilogue: silu, v store (fp16), score partials ----
#pragma unroll
    for (int it = 0; it < 4; it++)
#pragma unroll
        for (int jt = 0; jt < 8; jt++)
#pragma unroll
            for (int c = 0; c < 4; c++) {
                float x = acc[it][jt][c];
                acc[it][jt][c] = __fdividef(x, 1.f + __expf(-x));
            }

    const int head_l = wn >> 1;
    const int head_g = blockIdx.y * 2 + head_l;
    float ps[4][2];
#pragma unroll
    for (int it = 0; it < 4; it++) { ps[it][0] = 0.f; ps[it][1] = 0.f; }

#pragma unroll
    for (int it = 0; it < 4; it++) {
        const int row0 = m0 + wm * 64 + it * 16 + g;
#pragma unroll
        for (int jt = 0; jt < 8; jt++) {
            const int d  = (wn & 1) * 32 + jt * 4 + tg;
            const float qv = qw[head_g * D_ + d];
            ps[it][0] += qv * acc[it][jt][0];
            ps[it][1] += qv * acc[it][jt][2];
            g_v[((size_t)row0       * H_ + head_g) * D_ + d] = __float2half_rn(acc[it][jt][1]);
            g_v[((size_t)(row0 + 8) * H_ + head_g) * D_ + d] = __float2half_rn(acc[it][jt][3]);
        }
    }
#pragma unroll
    for (int it = 0; it < 4; it++)
#pragma unroll
        for (int hh = 0; hh < 2; hh++) {
            float v = ps[it][hh];
            v += __shfl_xor_sync(0xffffffffu, v, 1);
            v += __shfl_xor_sync(0xffffffffu, v, 2);
            ps[it][hh] = v;
        }
    if (tg == 0) {
#pragma unroll
        for (int it = 0; it < 4; it++) {
            S.sred[head_l][wm * 64 + it * 16 + g    ][wn & 1] = ps[it][0];
            S.sred[head_l][wm * 64 + it * 16 + g + 8][wn & 1] = ps[it][1];
        }
    }
    __syncthreads();

    {
        const int hl  = t >> 7;
        const int row = t & 127;
        float s = S.sred[hl][row][0] + S.sred[hl][row][1];
        g_s[(size_t)(m0 + row) * H_ + blockIdx.y * 2 + hl] = s;
    }
}

// ---------------------------------------------------------------------------
// Kernel 2: per-chunk (CH=32) aggregates from g_s + fp16 g_v.
// Also persists e = exp(s - m_chunk) for the apply kernel.
// Grid (NC, NBH), 256 threads: 4 row-quarters x 64 d.
// ---------------------------------------------------------------------------
__global__ __launch_bounds__(256)
void k_agg()
{
    const int c  = blockIdx.x;
    const int bh = blockIdx.y;
    const int b  = bh >> 4;
    const int h  = bh & 15;
    const int t  = threadIdx.x;
    const int d  = t & 63;
    const int tq = t >> 6;           // 0..3, 8 rows each
    const int t0 = c * CH;

    __shared__ float ssh[CH];
    __shared__ float esh[CH];
    __shared__ float wred[4][D_];

    if (t < CH) ssh[t] = g_s[(size_t)(b * T_ + t0 + t) * H_ + h];
    __syncthreads();

    float m = -1e30f;
#pragma unroll
    for (int i = 0; i < CH; i++) m = fmaxf(m, ssh[i]);
    if (t < CH) {
        float e = __expf(ssh[t] - m);
        esh[t] = e;
        g_e[(size_t)(b * T_ + t0 + t) * H_ + h] = e;
    }
    __syncthreads();

    float w = 0.f;
    const __half* vp = g_v + ((size_t)(b * T_ + t0 + tq * 8) * H_ + h) * D_ + d;
#pragma unroll
    for (int i = 0; i < 8; i++)
        w = fmaf(esh[tq * 8 + i], __half2float(vp[(size_t)i * (H_ * D_)]), w);
    wred[tq][d] = w;
    __syncthreads();

    const int idx = bh * NC + c;
    if (t < D_) {
        g_aw[idx * D_ + t] = wred[0][t] + wred[1][t] + wred[2][t] + wred[3][t];
        if (t == 0) {
            float u = 0.f;
#pragma unroll
            for (int i = 0; i < CH; i++) u += esh[i];
            g_am[idx] = m;
            g_au[idx] = u;
        }
    }
}

// ---------------------------------------------------------------------------
// Kernel 3: PARALLEL exclusive prefix — Hillis-Steele, split over 2 d-halves.
// Grid (NBH, 2), 256 threads, ping-pong, 7 steps (NC=128).
// ---------------------------------------------------------------------------
#define DH 32
struct PSmem {
    float w[2][NC][DH];   // 32768 B
    float m[2][NC];       // 1024 B
    float u[2][NC];       // 1024 B
    float ea[NC];         // 512 B
    float eb[NC];         // 512 B
};

__global__ __launch_bounds__(256)
void k_prefix()
{
    extern __shared__ __align__(16) char psm_raw[];
    PSmem& P = *reinterpret_cast<PSmem*>(psm_raw);

    const int bh = blockIdx.x;
    const int dh = blockIdx.y;       // d-half: 0 or 1
    const int t  = threadIdx.x;

    if (t < NC) {
        P.m[0][t] = g_am[bh * NC + t];
        P.u[0][t] = g_au[bh * NC + t];
    }
    {
        // load w half: 128 chunks x 32 d = 4096 floats = 1024 float4
        const float4* src = (const float4*)&g_aw[(size_t)bh * NC * D_];
        float4* dst = (float4*)&P.w[0][0][0];
#pragma unroll
        for (int q = 0; q < 4; q++) {
            int idx2 = t + q * 256;         // float4 index within half
            int c = idx2 >> 3, f4 = idx2 & 7;
            dst[idx2] = src[c * 16 + dh * 8 + f4];
        }
    }
    __syncthreads();

    int buf = 0;
#pragma unroll
    for (int k = 1; k < NC; k <<= 1) {
        if (t < NC) {
            float mb = P.m[buf][t], ub = P.u[buf][t];
            if (t >= k) {
                float ma = P.m[buf][t - k], ua = P.u[buf][t - k];
                float mn = fmaxf(ma, mb);
                float ea = __expf(ma - mn);
                float eb = __expf(mb - mn);
                P.m[buf ^ 1][t] = mn;
                P.u[buf ^ 1][t] = ua * ea + ub * eb;
                P.ea[t] = ea;
                P.eb[t] = eb;
            } else {
                P.m[buf ^ 1][t] = mb;
                P.u[buf ^ 1][t] = ub;
                P.ea[t] = 0.f;
                P.eb[t] = 1.f;
            }
        }
        __syncthreads();
#pragma unroll
        for (int q = 0; q < NC * DH / 256; q++) {       // 16
            int idx2 = t + q * 256;
            int c = idx2 >> 5, d = idx2 & 31;
            float wb = P.w[buf][c][d];
            float wa = (c >= k) ? P.w[buf][c - k][d] : 0.f;
            P.w[buf ^ 1][c][d] = fmaf(wa, P.ea[c], wb * P.eb[c]);
        }
        __syncthreads();
        buf ^= 1;
    }

    // write EXCLUSIVE prefix (shift by one chunk)
    if (dh == 0 && t < NC) {
        g_pm[bh * NC + t] = (t == 0) ? -1e30f : P.m[buf][t - 1];
        g_pu[bh * NC + t] = (t == 0) ? 0.f    : P.u[buf][t - 1];
    }
#pragma unroll
    for (int q = 0; q < NC * DH / 256; q++) {
        int idx2 = t + q * 256;
        int c = idx2 >> 5, d = idx2 & 31;
        g_pw[((size_t)bh * NC + c) * D_ + dh * DH + d] =
            (c == 0) ? 0.f : P.w[buf][c - 1][d];
    }
}

// ---------------------------------------------------------------------------
// Kernel 4: apply — fixed-reference-M form: no exp/max in the serial loop.
// 2 d-lanes/thread, 8 heads/block (256 thr), CH=32, fp16 v.
// ---------------------------------------------------------------------------
__global__ __launch_bounds__(256)
void k_apply(float* __restrict__ out)
{
    const int c    = blockIdx.x;
    const int bh0  = blockIdx.y * 8;
    const int t    = threadIdx.x;
    const int hh   = t >> 5;
    const int lane = t & 31;
    const int bh   = bh0 + hh;
    const int b    = bh >> 4;
    const int h    = bh & 15;
    const int t0   = c * CH;

    __shared__ float ssh[8][CH];
    {
        const int hx = t >> 5;
        const int i  = t & 31;
        const int bhx = bh0 + hx;
        ssh[hx][i] = g_e[(size_t)((bhx >> 4) * T_ + t0 + i) * H_ + (bhx & 15)];
    }
    __syncthreads();

    const int idx = bh * NC + c;
    float mp = g_pm[idx];
    float mc = g_am[idx];
    float M  = fmaxf(mp, mc);
    float sp = __expf(mp - M);     // prefix rescale
    float sc = __expf(mc - M);     // chunk-e rescale

    float u = g_pu[idx] * sp;
    float2 wv = *(const float2*)&g_pw[idx * D_ + 2 * lane];
    float w0 = wv.x * sp, w1 = wv.y * sp;

    const __half2* vp = (const __half2*)(g_v + ((size_t)(b * T_ + t0) * H_ + h) * D_ + 2 * lane);
    float2*        op = (float2*)(out + ((size_t)(b * T_ + t0) * H_ + h) * D_ + 2 * lane);
    const int      st = (H_ * D_) / 2;

#pragma unroll 8
    for (int i = 0; i < CH; i++) {
        float e = ssh[hh][i] * sc;
        u += e;
        float2 v2 = __half22float2(vp[(size_t)i * st]);
        w0 = fmaf(e, v2.x, w0);
        w1 = fmaf(e, v2.y, w1);
        float r = __fdividef(1.f, u);
        op[(size_t)i * st] = make_float2(w0 * r, w1 * r);
    }
}

// ---------------------------------------------------------------------------
extern "C" void kernel_launch(void* const* d_in, const int* in_sizes, int n_in,
                              void* d_out, int out_size)
{
    const float* inp = (const float*)d_in[0];   // (B,T,I)
    const float* kvw = (const float*)d_in[1];   // (I,H,D,2)
    const float* qw  = (const float*)d_in[2];   // (H,D)
    float* out = (float*)d_out;                 // (B,T,H,D)

    static int init = 0;
    if (!init) {
        cudaFuncSetAttribute(k_gemm_silu,
                             cudaFuncAttributeMaxDynamicSharedMemorySize,
                             (int)sizeof(GSmem));
        cudaFuncSetAttribute(k_prefix,
                             cudaFuncAttributeMaxDynamicSharedMemorySize,
                             (int)sizeof(PSmem));
        init = 1;
    }

    const int nsplit = (int)((NA4 + NB4 + 255) / 256);
    k_split<<<nsplit, 256>>>(inp, kvw);
    k_gemm_silu<<<dim3(M_ / 128, NTOT / 256), 256, sizeof(GSmem)>>>(qw);
    k_agg   <<<dim3(NC, NBH), 256>>>();
    k_prefix<<<dim3(NBH, 2), 256, sizeof(PSmem)>>>();
    k_apply <<<dim3(NC, NBH / 8), 256>>>(out);
}